// round 11
// baseline (speedup 1.0000x reference)
#include <cuda_runtime.h>
#include <cuda_bf16.h>
#include <cstdint>

typedef unsigned long long ull;

#define NB   256
#define TT   254
#define AUGS 148
#define CH   145
#define SIGK 21170
#define SIGS 21312          // padded K: 37*576, mult of 32
#define SPLITK 37
#define KCH  576
#define NCH  18
#define RST  40
#define ARR_B (128 * RST * 2)
#define BUF_B (4 * ARR_B)

__device__ float g_aug[NB * TT * AUGS];
__device__ __align__(16) __nv_bfloat16 g_shi[(size_t)NB * SIGS];
__device__ __align__(16) __nv_bfloat16 g_slo[(size_t)NB * SIGS];
__device__ __align__(16) __nv_bfloat16 g_whi[(size_t)256 * SIGS];
__device__ __align__(16) __nv_bfloat16 g_wlo[(size_t)256 * SIGS];
__device__ float g_part[(size_t)SPLITK * 256 * 256];

__device__ __forceinline__ ull pack2(float lo, float hi) {
    ull r; asm("mov.b64 %0, {%1, %2};" : "=l"(r) : "f"(lo), "f"(hi)); return r;
}
__device__ __forceinline__ void unpack2(ull v, float& lo, float& hi) {
    asm("mov.b64 {%0, %1}, %2;" : "=f"(lo), "=f"(hi) : "l"(v));
}
__device__ __forceinline__ void ffma2(ull& acc, ull a, ull b) {
    asm("fma.rn.f32x2 %0, %1, %2, %0;" : "+l"(acc) : "l"(a), "l"(b));
}
__device__ __forceinline__ uint32_t ld32h(const __nv_bfloat16* p) {
    return *(const uint32_t*)p;
}
__device__ __forceinline__ void mma16816(float* d, const uint32_t* a,
                                         const uint32_t* b) {
    asm volatile(
        "mma.sync.aligned.m16n8k16.row.col.f32.bf16.bf16.f32 "
        "{%0,%1,%2,%3}, {%4,%5,%6,%7}, {%8,%9}, {%0,%1,%2,%3};"
        : "+f"(d[0]), "+f"(d[1]), "+f"(d[2]), "+f"(d[3])
        : "r"(a[0]), "r"(a[1]), "r"(a[2]), "r"(a[3]), "r"(b[0]), "r"(b[1]));
}
__device__ __forceinline__ void st_split(__nv_bfloat16* ph, __nv_bfloat16* pl, float v) {
    __nv_bfloat16 h = __float2bfloat16(v);
    *ph = h;
    *pl = __float2bfloat16(v - __bfloat162float(h));
}

// ============================================================
// K1: conv1(3,16->64) + conv2(1x1,64->128,relu) -> g_aug
// ============================================================
#define HS 72
__global__ __launch_bounds__(256, 2) void k_front(
    const float* __restrict__ q,
    const float* __restrict__ w1, const float* __restrict__ b1,
    const float* __restrict__ w2, const float* __restrict__ b2)
{
    extern __shared__ float sm[];
    float* sXd = sm;
    float* sW1 = sm + 8192;
    float* sW2 = sm + 11264;
    float* sH  = sm + 19456;
    float* sB1 = sm + 24064;
    float* sB2 = sm + 24128;

    int n = blockIdx.x, tid = threadIdx.x;
    int b = n >> 3, hh = n & 7;

    for (int idx = tid; idx < 4096; idx += 256) {
        int t = idx >> 4, e = idx & 15;
        float v = q[(((size_t)b * 256 + t) * 8 + hh) * 16 + e];
        *(ull*)&sXd[2 * idx] = pack2(v, v);
    }
    for (int idx = tid; idx < 3072; idx += 256) sW1[idx] = w1[idx];
    for (int idx = tid; idx < 8192; idx += 256) sW2[idx] = w2[idx];
    if (tid < 64) sB1[tid] = b1[tid];
    else if (tid < 192) sB2[tid - 64] = b2[tid - 64];
    __syncthreads();

    float* aug = g_aug + (size_t)n * (TT * AUGS);

    for (int t = tid >> 5; t < TT; t += 8) {
        for (int c = tid & 31; c < 17; c += 32) {
            aug[t * AUGS + c] = (c < 16) ? sXd[2 * ((t + 2) * 16 + c)]
                                         : (float)t * (1.0f / 253.0f);
        }
    }

    int mg = tid & 7,  tg  = tid >> 3;
    int cg = tid & 15, tgq = tid >> 4;

    for (int t0 = 0; t0 < TT; t0 += 64) {
        int tc = min(64, TT - t0);
        __syncthreads();
        {
            ull acc[2][4];
            #pragma unroll
            for (int j = 0; j < 4; j++) {
                ull bia = pack2(sB1[2 * (mg + 8 * j)], sB1[2 * (mg + 8 * j) + 1]);
                acc[0][j] = bia; acc[1][j] = bia;
            }
            const ull* xr0 = (const ull*)sXd + (t0 + 2 * tg) * 16;
            const ull* xr1 = xr0 + 16;
            #pragma unroll
            for (int we = 0; we < 48; we++) {
                ull xa = xr0[we], xb = xr1[we];
                #pragma unroll
                for (int j = 0; j < 4; j++) {
                    ull wv = *(const ull*)&sW1[we * 64 + 2 * (mg + 8 * j)];
                    ffma2(acc[0][j], xa, wv);
                    ffma2(acc[1][j], xb, wv);
                }
            }
            #pragma unroll
            for (int tl = 0; tl < 2; tl++) {
                int t = 2 * tg + tl;
                if (t < tc) {
                    float* hr = &sH[t * HS];
                    #pragma unroll
                    for (int j = 0; j < 4; j++)
                        *(ull*)&hr[2 * (mg + 8 * j)] = acc[tl][j];
                }
            }
        }
        __syncthreads();
        {
            ull acc[4][4];
            #pragma unroll
            for (int j = 0; j < 4; j++) {
                ull bia = pack2(sB2[2 * (cg + 16 * j)], sB2[2 * (cg + 16 * j) + 1]);
                #pragma unroll
                for (int i = 0; i < 4; i++) acc[i][j] = bia;
            }
            #pragma unroll
            for (int m = 0; m < 64; m++) {
                ull wv[4];
                #pragma unroll
                for (int j = 0; j < 4; j++)
                    wv[j] = *(const ull*)&sW2[m * 128 + 2 * (cg + 16 * j)];
                #pragma unroll
                for (int i = 0; i < 4; i++) {
                    float h = sH[(4 * tgq + i) * HS + m];
                    ull hv = pack2(h, h);
                    #pragma unroll
                    for (int j = 0; j < 4; j++) ffma2(acc[i][j], hv, wv[j]);
                }
            }
            #pragma unroll
            for (int i = 0; i < 4; i++) {
                int t = 4 * tgq + i;
                if (t < tc) {
                    float* ar = aug + (size_t)(t0 + t) * AUGS + 17;
                    #pragma unroll
                    for (int j = 0; j < 4; j++) {
                        float lo, hi; unpack2(acc[i][j], lo, hi);
                        int c = 2 * (cg + 16 * j);
                        ar[c]     = fmaxf(lo, 0.f);
                        ar[c + 1] = fmaxf(hi, 0.f);
                    }
                }
            }
        }
    }
}

// ============================================================
// K2: signature via mma.sync: S = U^T D (M=N=160pad, K=256pad)
// per-n CTA, 8 warps (2m x 4n), smem U/D transposed bf16 hi/lo
// ============================================================
#define SRST 40
// dynamic smem: halves [sUh 6400][sUl 6400][sDh 6400][sDl 6400] + sA0 floats
#define SIG_SMEMB (4 * 160 * SRST * 2 + 160 * 4)

__global__ __launch_bounds__(256) void k_sigmma()
{
    extern __shared__ __align__(16) char smraw[];
    __nv_bfloat16* sUh = (__nv_bfloat16*)smraw;
    __nv_bfloat16* sUl = sUh + 160 * SRST;
    __nv_bfloat16* sDh = sUl + 160 * SRST;
    __nv_bfloat16* sDl = sDh + 160 * SRST;
    float* sA0 = (float*)(sDl + 160 * SRST);

    int n = blockIdx.x, tid = threadIdx.x;
    const float* aug = g_aug + (size_t)n * (TT * AUGS);
    __nv_bfloat16* sh = g_shi + (size_t)n * SIGS;
    __nv_bfloat16* sl = g_slo + (size_t)n * SIGS;

    if (tid < 160) sA0[tid] = (tid < CH) ? aug[tid] : 0.f;
    if (tid < CH) {
        float v = aug[253 * AUGS + tid] - aug[tid];   // s1
        st_split(sh + tid, sl + tid, v);
    }
    const __nv_bfloat16 z16 = __float2bfloat16(0.f);
    for (int i = SIGK + tid; i < SIGS; i += 256) { sh[i] = z16; sl[i] = z16; }

    int wid = tid >> 5, lane = tid & 31, qq = lane >> 2, rs = lane & 3;
    int wm = wid & 1, wn = wid >> 1;
    int tp = tid >> 3, cp = tid & 7;

    float acc[5][5][4];
    #pragma unroll
    for (int mt = 0; mt < 5; mt++)
        #pragma unroll
        for (int nt = 0; nt < 5; nt++)
            #pragma unroll
            for (int j = 0; j < 4; j++) acc[mt][nt][j] = 0.f;

    for (int ch = 0; ch < 8; ch++) {
        __syncthreads();   // protect smem from previous iter's fragment reads
        // ---- prep: u/d for t = 32*ch + tp, transposed split stores ----
        {
            int t = 32 * ch + tp;
            bool tok = (t < 253);
            const float* r0 = aug + (size_t)(tok ? t : 0) * AUGS;
            #pragma unroll
            for (int s = 0; s < 20; s++) {
                int c = cp + 8 * s;
                bool ok = tok && (c < CH);
                float a0 = ok ? r0[c] : 0.f;
                float a1 = ok ? r0[AUGS + c] : 0.f;
                float d = a1 - a0;
                float u = 0.5f * (a0 + a1) - (ok ? sA0[c] : 0.f);
                if (!ok) u = 0.f;
                int o = c * SRST + tp;
                __nv_bfloat16 hv = __float2bfloat16(u);
                sUh[o] = hv;
                sUl[o] = __float2bfloat16(u - __bfloat162float(hv));
                hv = __float2bfloat16(d);
                sDh[o] = hv;
                sDl[o] = __float2bfloat16(d - __bfloat162float(hv));
            }
        }
        __syncthreads();
        // ---- mma: 2 k16 steps ----
        #pragma unroll
        for (int kk = 0; kk < 2; kk++) {
            int col = 2 * rs + 16 * kk;
            uint32_t bh[5][2], bl[5][2];
            #pragma unroll
            for (int nt = 0; nt < 5; nt++) {
                int rn = (40 * wn + 8 * nt + qq) * SRST + col;
                bh[nt][0] = ld32h(sDh + rn);
                bh[nt][1] = ld32h(sDh + rn + 8);
                bl[nt][0] = ld32h(sDl + rn);
                bl[nt][1] = ld32h(sDl + rn + 8);
            }
            #pragma unroll
            for (int mt = 0; mt < 5; mt++) {
                int r0 = (80 * wm + 16 * mt + qq) * SRST + col;
                uint32_t ah[4], al[4];
                ah[0] = ld32h(sUh + r0);
                ah[1] = ld32h(sUh + r0 + 8 * SRST);
                ah[2] = ld32h(sUh + r0 + 8);
                ah[3] = ld32h(sUh + r0 + 8 * SRST + 8);
                al[0] = ld32h(sUl + r0);
                al[1] = ld32h(sUl + r0 + 8 * SRST);
                al[2] = ld32h(sUl + r0 + 8);
                al[3] = ld32h(sUl + r0 + 8 * SRST + 8);
                #pragma unroll
                for (int nt = 0; nt < 5; nt++) {
                    mma16816(acc[mt][nt], ah, bh[nt]);
                    mma16816(acc[mt][nt], ah, bl[nt]);
                    mma16816(acc[mt][nt], al, bh[nt]);
                }
            }
        }
    }

    // ---- epilogue: write S split to g_shi/g_slo ----
    #pragma unroll
    for (int mt = 0; mt < 5; mt++) {
        int i0 = 80 * wm + 16 * mt + qq;
        #pragma unroll
        for (int nt = 0; nt < 5; nt++) {
            int j0 = 40 * wn + 8 * nt + 2 * rs;
            #pragma unroll
            for (int hrow = 0; hrow < 2; hrow++) {
                int i = i0 + 8 * hrow;
                if (i >= CH) continue;
                int rb = 145 + i * 145;
                float v0 = acc[mt][nt][2 * hrow];
                float v1 = acc[mt][nt][2 * hrow + 1];
                if (j0 < CH)     st_split(sh + rb + j0,     sl + rb + j0,     v0);
                if (j0 + 1 < CH) st_split(sh + rb + j0 + 1, sl + rb + j0 + 1, v1);
            }
        }
    }
}

// ============================================================
// K3: W prep — transpose lin_w[21170][256] -> bf16 hi/lo [o][k]
// ============================================================
__global__ __launch_bounds__(256) void k_wprep(const float* __restrict__ W)
{
    __shared__ float sw[32 * 256];
    int k0 = blockIdx.x * 32, tid = threadIdx.x;
    for (int r = 0; r < 32; r++) {
        int k = k0 + r;
        sw[r * 256 + tid] = (k < SIGK) ? W[(size_t)k * 256 + tid] : 0.f;
    }
    __syncthreads();
    __nv_bfloat16* dh = g_whi + (size_t)tid * SIGS + k0;
    __nv_bfloat16* dl = g_wlo + (size_t)tid * SIGS + k0;
    for (int r = 0; r < 32; r += 8) {
        unsigned hu[4], lu[4];
        #pragma unroll
        for (int j = 0; j < 4; j++) {
            float v0 = sw[(r + 2 * j) * 256 + tid];
            float v1 = sw[(r + 2 * j + 1) * 256 + tid];
            __nv_bfloat16 h0 = __float2bfloat16(v0), h1 = __float2bfloat16(v1);
            __nv_bfloat16 l0 = __float2bfloat16(v0 - __bfloat162float(h0));
            __nv_bfloat16 l1 = __float2bfloat16(v1 - __bfloat162float(h1));
            hu[j] = (unsigned)__bfloat16_as_ushort(h0) |
                    ((unsigned)__bfloat16_as_ushort(h1) << 16);
            lu[j] = (unsigned)__bfloat16_as_ushort(l0) |
                    ((unsigned)__bfloat16_as_ushort(l1) << 16);
        }
        *(uint4*)(dh + r) = make_uint4(hu[0], hu[1], hu[2], hu[3]);
        *(uint4*)(dl + r) = make_uint4(lu[0], lu[1], lu[2], lu[3]);
    }
}

// ============================================================
// K4: mma.sync bf16-split GEMM  part[z] = sig @ W^T (128x128 tiles)
// ============================================================
__device__ __forceinline__ uint32_t smem_u32(const void* p) {
    uint32_t a;
    asm("{ .reg .u64 t; cvta.to.shared.u64 t, %1; cvt.u32.u64 %0, t; }"
        : "=r"(a) : "l"(p));
    return a;
}

__global__ __launch_bounds__(256) void k_mma()
{
    extern __shared__ __align__(16) char smem[];
    uint32_t sb = smem_u32(smem);
    int tid = threadIdx.x, wid = tid >> 5, lane = tid & 31;
    int q = lane >> 2, rs = lane & 3;
    int wm = wid & 3, wn = wid >> 2;
    int n0 = blockIdx.x * 128, o0 = blockIdx.y * 128, z = blockIdx.z;
    int kb = z * KCH;

    const __nv_bfloat16* gb0 = g_shi + (size_t)n0 * SIGS;
    const __nv_bfloat16* gb1 = g_slo + (size_t)n0 * SIGS;
    const __nv_bfloat16* gb2 = g_whi + (size_t)o0 * SIGS;
    const __nv_bfloat16* gb3 = g_wlo + (size_t)o0 * SIGS;

    auto issue = [&](int c) {
        uint32_t sdst = sb + (c & 1) * BUF_B;
        int k0 = kb + c * 32;
        #pragma unroll
        for (int i = 0; i < 8; i++) {
            int idx = tid + 256 * i;
            int arr = idx >> 9;
            int r = (idx >> 2) & 127;
            int seg = idx & 3;
            const __nv_bfloat16* gp =
                (arr == 0 ? gb0 : arr == 1 ? gb1 : arr == 2 ? gb2 : gb3)
                + (size_t)r * SIGS + k0 + seg * 8;
            uint32_t sp = sdst + arr * ARR_B + r * (RST * 2) + seg * 16;
            asm volatile("cp.async.cg.shared.global [%0], [%1], 16;"
                         :: "r"(sp), "l"(gp));
        }
        asm volatile("cp.async.commit_group;" ::: "memory");
    };

    float acc[2][8][4];
    #pragma unroll
    for (int mt = 0; mt < 2; mt++)
        #pragma unroll
        for (int nt = 0; nt < 8; nt++)
            #pragma unroll
            for (int j = 0; j < 4; j++) acc[mt][nt][j] = 0.f;

    issue(0);
    issue(1);

    for (int c = 0; c < NCH; c++) {
        if (c + 2 < NCH)
            asm volatile("cp.async.wait_group 1;" ::: "memory");
        else
            asm volatile("cp.async.wait_group 0;" ::: "memory");
        __syncthreads();

        const __nv_bfloat16* Ah =
            (const __nv_bfloat16*)(smem + (c & 1) * BUF_B);
        const __nv_bfloat16* Al = Ah + 128 * RST;
        const __nv_bfloat16* Bh = Al + 128 * RST;
        const __nv_bfloat16* Bl = Bh + 128 * RST;

        #pragma unroll
        for (int kk = 0; kk < 2; kk++) {
            int col = 2 * rs + 16 * kk;
            uint32_t af[2][2][4];
            #pragma unroll
            for (int mt = 0; mt < 2; mt++) {
                int r0 = 32 * wm + 16 * mt + q;
                af[mt][0][0] = ld32h(Ah + r0 * RST + col);
                af[mt][0][1] = ld32h(Ah + (r0 + 8) * RST + col);
                af[mt][0][2] = ld32h(Ah + r0 * RST + col + 8);
                af[mt][0][3] = ld32h(Ah + (r0 + 8) * RST + col + 8);
                af[mt][1][0] = ld32h(Al + r0 * RST + col);
                af[mt][1][1] = ld32h(Al + (r0 + 8) * RST + col);
                af[mt][1][2] = ld32h(Al + r0 * RST + col + 8);
                af[mt][1][3] = ld32h(Al + (r0 + 8) * RST + col + 8);
            }
            uint32_t bfr[8][2][2];
            #pragma unroll
            for (int nt = 0; nt < 8; nt++) {
                int rn = 64 * wn + 8 * nt + q;
                bfr[nt][0][0] = ld32h(Bh + rn * RST + col);
                bfr[nt][0][1] = ld32h(Bh + rn * RST + col + 8);
                bfr[nt][1][0] = ld32h(Bl + rn * RST + col);
                bfr[nt][1][1] = ld32h(Bl + rn * RST + col + 8);
            }
            #pragma unroll
            for (int mt = 0; mt < 2; mt++)
                #pragma unroll
                for (int nt = 0; nt < 8; nt++) {
                    mma16816(acc[mt][nt], af[mt][0], bfr[nt][0]);
                    mma16816(acc[mt][nt], af[mt][0], bfr[nt][1]);
                    mma16816(acc[mt][nt], af[mt][1], bfr[nt][0]);
                }
        }
        __syncthreads();
        if (c + 2 < NCH) issue(c + 2);
    }

    float* pz = g_part + ((size_t)z * 256 + n0 + 32 * wm) * 256 + o0 + 64 * wn;
    #pragma unroll
    for (int mt = 0; mt < 2; mt++) {
        #pragma unroll
        for (int nt = 0; nt < 8; nt++) {
            int m = 16 * mt + q;
            int cc = 8 * nt + 2 * rs;
            float2 v01 = make_float2(acc[mt][nt][0], acc[mt][nt][1]);
            float2 v23 = make_float2(acc[mt][nt][2], acc[mt][nt][3]);
            *(float2*)&pz[(size_t)m * 256 + cc] = v01;
            *(float2*)&pz[(size_t)(m + 8) * 256 + cc] = v23;
        }
    }
}

// ============================================================
// K5: reduce splitK partials + bias
// ============================================================
__global__ void k_red(const float* __restrict__ lb, float* __restrict__ out)
{
    int n = blockIdx.x, o = threadIdx.x;
    float s = lb[o];
    #pragma unroll 4
    for (int z = 0; z < SPLITK; z++)
        s += g_part[((size_t)z * 256 + n) * 256 + o];
    out[n * 256 + o] = s;
}

// ============================================================
extern "C" void kernel_launch(void* const* d_in, const int* in_sizes, int n_in,
                              void* d_out, int out_size)
{
    const float* q  = (const float*)d_in[0];
    const float* w1 = (const float*)d_in[4];
    const float* b1 = (const float*)d_in[5];
    const float* w2 = (const float*)d_in[6];
    const float* b2 = (const float*)d_in[7];
    const float* lw = (const float*)d_in[8];
    const float* lb = (const float*)d_in[9];
    float* out = (float*)d_out;

    cudaFuncSetAttribute(k_front, cudaFuncAttributeMaxDynamicSharedMemorySize,
                         24256 * 4);
    cudaFuncSetAttribute(k_sigmma, cudaFuncAttributeMaxDynamicSharedMemorySize,
                         SIG_SMEMB);
    cudaFuncSetAttribute(k_mma, cudaFuncAttributeMaxDynamicSharedMemorySize,
                         2 * BUF_B);
    k_front<<<NB, 256, 24256 * 4>>>(q, w1, b1, w2, b2);
    k_sigmma<<<NB, 256, SIG_SMEMB>>>();
    k_wprep<<<SIGS / 32, 256>>>(lw);
    k_mma<<<dim3(2, 2, SPLITK), 256, 2 * BUF_B>>>();
    k_red<<<256, 256>>>(lb, out);
}

// round 12
// speedup vs baseline: 1.1632x; 1.1632x over previous
#include <cuda_runtime.h>
#include <cuda_bf16.h>
#include <cstdint>

typedef unsigned long long ull;

#define NB   256
#define TT   254
#define AUGS 148
#define CH   145
#define SIGS 21888          // padded K': 36*608; layout 148-stride rows
#define SIGEND 21608        // 148 + 145*148
#define SPLITK 36
#define KCH  608
#define NCH  19
#define RST  40
#define ARR_B (128 * RST * 2)
#define BUF_B (4 * ARR_B)

__device__ float g_aug[NB * TT * AUGS];
__device__ __align__(16) __nv_bfloat16 g_shi[(size_t)NB * SIGS];
__device__ __align__(16) __nv_bfloat16 g_slo[(size_t)NB * SIGS];
__device__ __align__(16) __nv_bfloat16 g_whi[(size_t)256 * SIGS];
__device__ __align__(16) __nv_bfloat16 g_wlo[(size_t)256 * SIGS];
__device__ float g_part[(size_t)SPLITK * 256 * 256];

__device__ __forceinline__ ull pack2(float lo, float hi) {
    ull r; asm("mov.b64 %0, {%1, %2};" : "=l"(r) : "f"(lo), "f"(hi)); return r;
}
__device__ __forceinline__ void unpack2(ull v, float& lo, float& hi) {
    asm("mov.b64 {%0, %1}, %2;" : "=f"(lo), "=f"(hi) : "l"(v));
}
__device__ __forceinline__ void ffma2(ull& acc, ull a, ull b) {
    asm("fma.rn.f32x2 %0, %1, %2, %0;" : "+l"(acc) : "l"(a), "l"(b));
}
__device__ __forceinline__ uint32_t ld32h(const __nv_bfloat16* p) {
    return *(const uint32_t*)p;
}
__device__ __forceinline__ void mma16816(float* d, const uint32_t* a,
                                         const uint32_t* b) {
    asm volatile(
        "mma.sync.aligned.m16n8k16.row.col.f32.bf16.bf16.f32 "
        "{%0,%1,%2,%3}, {%4,%5,%6,%7}, {%8,%9}, {%0,%1,%2,%3};"
        : "+f"(d[0]), "+f"(d[1]), "+f"(d[2]), "+f"(d[3])
        : "r"(a[0]), "r"(a[1]), "r"(a[2]), "r"(a[3]), "r"(b[0]), "r"(b[1]));
}
__device__ __forceinline__ void st_split(__nv_bfloat16* ph, __nv_bfloat16* pl, float v) {
    __nv_bfloat16 h = __float2bfloat16(v);
    *ph = h;
    *pl = __float2bfloat16(v - __bfloat162float(h));
}
__device__ __forceinline__ uint32_t packbf(float a, float b) {
    __nv_bfloat16 x = __float2bfloat16(a), y = __float2bfloat16(b);
    return (uint32_t)__bfloat16_as_ushort(x) |
           ((uint32_t)__bfloat16_as_ushort(y) << 16);
}

// ============================================================
// K1: conv1(3,16->64) + conv2(1x1,64->128,relu) -> g_aug
// ============================================================
#define HS 72
__global__ __launch_bounds__(256, 2) void k_front(
    const float* __restrict__ q,
    const float* __restrict__ w1, const float* __restrict__ b1,
    const float* __restrict__ w2, const float* __restrict__ b2)
{
    extern __shared__ float sm[];
    float* sXd = sm;
    float* sW1 = sm + 8192;
    float* sW2 = sm + 11264;
    float* sH  = sm + 19456;
    float* sB1 = sm + 24064;
    float* sB2 = sm + 24128;

    int n = blockIdx.x, tid = threadIdx.x;
    int b = n >> 3, hh = n & 7;

    for (int idx = tid; idx < 4096; idx += 256) {
        int t = idx >> 4, e = idx & 15;
        float v = q[(((size_t)b * 256 + t) * 8 + hh) * 16 + e];
        *(ull*)&sXd[2 * idx] = pack2(v, v);
    }
    for (int idx = tid; idx < 3072; idx += 256) sW1[idx] = w1[idx];
    for (int idx = tid; idx < 8192; idx += 256) sW2[idx] = w2[idx];
    if (tid < 64) sB1[tid] = b1[tid];
    else if (tid < 192) sB2[tid - 64] = b2[tid - 64];
    __syncthreads();

    float* aug = g_aug + (size_t)n * (TT * AUGS);

    for (int t = tid >> 5; t < TT; t += 8) {
        for (int c = tid & 31; c < 17; c += 32) {
            aug[t * AUGS + c] = (c < 16) ? sXd[2 * ((t + 2) * 16 + c)]
                                         : (float)t * (1.0f / 253.0f);
        }
    }

    int mg = tid & 7,  tg  = tid >> 3;
    int cg = tid & 15, tgq = tid >> 4;

    for (int t0 = 0; t0 < TT; t0 += 64) {
        int tc = min(64, TT - t0);
        __syncthreads();
        {
            ull acc[2][4];
            #pragma unroll
            for (int j = 0; j < 4; j++) {
                ull bia = pack2(sB1[2 * (mg + 8 * j)], sB1[2 * (mg + 8 * j) + 1]);
                acc[0][j] = bia; acc[1][j] = bia;
            }
            const ull* xr0 = (const ull*)sXd + (t0 + 2 * tg) * 16;
            const ull* xr1 = xr0 + 16;
            #pragma unroll
            for (int we = 0; we < 48; we++) {
                ull xa = xr0[we], xb = xr1[we];
                #pragma unroll
                for (int j = 0; j < 4; j++) {
                    ull wv = *(const ull*)&sW1[we * 64 + 2 * (mg + 8 * j)];
                    ffma2(acc[0][j], xa, wv);
                    ffma2(acc[1][j], xb, wv);
                }
            }
            #pragma unroll
            for (int tl = 0; tl < 2; tl++) {
                int t = 2 * tg + tl;
                if (t < tc) {
                    float* hr = &sH[t * HS];
                    #pragma unroll
                    for (int j = 0; j < 4; j++)
                        *(ull*)&hr[2 * (mg + 8 * j)] = acc[tl][j];
                }
            }
        }
        __syncthreads();
        {
            ull acc[4][4];
            #pragma unroll
            for (int j = 0; j < 4; j++) {
                ull bia = pack2(sB2[2 * (cg + 16 * j)], sB2[2 * (cg + 16 * j) + 1]);
                #pragma unroll
                for (int i = 0; i < 4; i++) acc[i][j] = bia;
            }
            #pragma unroll
            for (int m = 0; m < 64; m++) {
                ull wv[4];
                #pragma unroll
                for (int j = 0; j < 4; j++)
                    wv[j] = *(const ull*)&sW2[m * 128 + 2 * (cg + 16 * j)];
                #pragma unroll
                for (int i = 0; i < 4; i++) {
                    float h = sH[(4 * tgq + i) * HS + m];
                    ull hv = pack2(h, h);
                    #pragma unroll
                    for (int j = 0; j < 4; j++) ffma2(acc[i][j], hv, wv[j]);
                }
            }
            #pragma unroll
            for (int i = 0; i < 4; i++) {
                int t = 4 * tgq + i;
                if (t < tc) {
                    float* ar = aug + (size_t)(t0 + t) * AUGS + 17;
                    #pragma unroll
                    for (int j = 0; j < 4; j++) {
                        float lo, hi; unpack2(acc[i][j], lo, hi);
                        int c = 2 * (cg + 16 * j);
                        ar[c]     = fmaxf(lo, 0.f);
                        ar[c + 1] = fmaxf(hi, 0.f);
                    }
                }
            }
        }
    }
}

// ============================================================
// K2: signature (FFMA2) -> bf16 hi/lo, 148-stride rows, packed
//     u32 coalesced epilogue stores
// ============================================================
__global__ __launch_bounds__(256) void k_sig()
{
    __shared__ float sD[2][8][168];
    __shared__ float sU[2][8][168];
    __shared__ float sA0[168];

    int n = blockIdx.x, tid = threadIdx.x;
    const float* aug = g_aug + (size_t)n * (TT * AUGS);
    __nv_bfloat16* sh = g_shi + (size_t)n * SIGS;
    __nv_bfloat16* sl = g_slo + (size_t)n * SIGS;

    if (tid < 168) sA0[tid] = (tid < CH) ? aug[tid] : 0.f;
    if (tid < CH) {
        float v = aug[253 * AUGS + tid] - aug[tid];   // s1
        st_split(sh + tid, sl + tid, v);
    }
    const __nv_bfloat16 z16 = __float2bfloat16(0.f);
    if (tid < 3) { sh[145 + tid] = z16; sl[145 + tid] = z16; }   // s1 row pad
    for (int i = SIGEND + tid; i < SIGS; i += 256) { sh[i] = z16; sl[i] = z16; }

    int kk = tid >> 5, cx = tid & 31;
    int ty = tid >> 4, tx = tid & 15;

    float pa[5], pb[5];
    {
        const float* rr = aug + (size_t)kk * AUGS;
        #pragma unroll
        for (int s = 0; s < 5; s++) {
            int c = cx + 32 * s;
            bool ok = (c < CH);
            pa[s] = ok ? rr[c] : 0.f;
            pb[s] = ok ? rr[AUGS + c] : 0.f;
        }
    }
    __syncthreads();
    #pragma unroll
    for (int s = 0; s < 5; s++) {
        int c = cx + 32 * s;
        sD[0][kk][c] = pb[s] - pa[s];
        sU[0][kk][c] = 0.5f * (pa[s] + pb[s]) - sA0[c];
    }
    __syncthreads();

    ull acc[10][5];
    #pragma unroll
    for (int r = 0; r < 10; r++)
        #pragma unroll
        for (int s = 0; s < 5; s++) acc[r][s] = 0ull;

    for (int it = 0; it < 32; it++) {
        int cur = it & 1;
        float na[5], nb[5];
        if (it + 1 < 32) {
            int t = 8 * (it + 1) + kk;
            bool tok = (t < 253);
            const float* rr = aug + (size_t)(tok ? t : 0) * AUGS;
            #pragma unroll
            for (int s = 0; s < 5; s++) {
                int c = cx + 32 * s;
                bool ok = tok && (c < CH);
                na[s] = ok ? rr[c] : 0.f;
                nb[s] = ok ? rr[AUGS + c] : 0.f;
            }
        }
        #pragma unroll
        for (int k2 = 0; k2 < 8; k2++) {
            ull d2[5];
            #pragma unroll
            for (int s = 0; s < 5; s++)
                d2[s] = *(const ull*)&sD[cur][k2][2 * (tx + 16 * s)];
            #pragma unroll
            for (int r = 0; r < 10; r++) {
                float u = sU[cur][k2][ty + 16 * r];
                ull uu = pack2(u, u);
                #pragma unroll
                for (int s = 0; s < 5; s++) ffma2(acc[r][s], uu, d2[s]);
            }
        }
        if (it + 1 < 32) {
            int nxt = cur ^ 1;
            #pragma unroll
            for (int s = 0; s < 5; s++) {
                int c = cx + 32 * s;
                sD[nxt][kk][c] = nb[s] - na[s];
                sU[nxt][kk][c] = 0.5f * (na[s] + nb[s]) - sA0[c];
            }
        }
        __syncthreads();
    }

    // packed, coalesced epilogue (rows at 148 stride; pads zeroed by clamp)
    #pragma unroll
    for (int r = 0; r < 10; r++) {
        int i = ty + 16 * r;
        if (i >= CH) continue;
        int rb = 148 + i * 148;
        #pragma unroll
        for (int s = 0; s < 5; s++) {
            int j = 2 * (tx + 16 * s);
            if (j >= 148) continue;
            float lo, hi; unpack2(acc[r][s], lo, hi);
            if (j >= CH) lo = 0.f;
            if (j + 1 >= CH) hi = 0.f;
            __nv_bfloat16 h0 = __float2bfloat16(lo);
            __nv_bfloat16 h1 = __float2bfloat16(hi);
            *(uint32_t*)(sh + rb + j) =
                (uint32_t)__bfloat16_as_ushort(h0) |
                ((uint32_t)__bfloat16_as_ushort(h1) << 16);
            *(uint32_t*)(sl + rb + j) =
                packbf(lo - __bfloat162float(h0), hi - __bfloat162float(h1));
        }
    }
}

// ============================================================
// K3: W prep — map W rows into 148-stride layout, bf16 hi/lo [o][p]
// ============================================================
__global__ __launch_bounds__(256) void k_wprep(const float* __restrict__ W)
{
    __shared__ float sw[32 * 256];
    int p0 = blockIdx.x * 32, tid = threadIdx.x;
    for (int r = 0; r < 32; r++) {
        int p = p0 + r;
        float v = 0.f;
        if (p < 145) {
            v = W[(size_t)p * 256 + tid];
        } else if (p >= 148 && p < SIGEND) {
            int rem = p - 148;
            int i = rem / 148, j = rem - i * 148;
            if (j < 145) v = W[(size_t)(145 + i * 145 + j) * 256 + tid];
        }
        sw[r * 256 + tid] = v;
    }
    __syncthreads();
    __nv_bfloat16* dh = g_whi + (size_t)tid * SIGS + p0;
    __nv_bfloat16* dl = g_wlo + (size_t)tid * SIGS + p0;
    for (int r = 0; r < 32; r += 8) {
        unsigned hu[4], lu[4];
        #pragma unroll
        for (int j = 0; j < 4; j++) {
            float v0 = sw[(r + 2 * j) * 256 + tid];
            float v1 = sw[(r + 2 * j + 1) * 256 + tid];
            __nv_bfloat16 h0 = __float2bfloat16(v0), h1 = __float2bfloat16(v1);
            hu[j] = (unsigned)__bfloat16_as_ushort(h0) |
                    ((unsigned)__bfloat16_as_ushort(h1) << 16);
            lu[j] = packbf(v0 - __bfloat162float(h0), v1 - __bfloat162float(h1));
        }
        *(uint4*)(dh + r) = make_uint4(hu[0], hu[1], hu[2], hu[3]);
        *(uint4*)(dl + r) = make_uint4(lu[0], lu[1], lu[2], lu[3]);
    }
}

// ============================================================
// K4: mma.sync bf16-split GEMM  part[z] = sig @ W^T (128x128 tiles)
// grid (2, 2, SPLITK) = 144 CTAs, 256 thr
// ============================================================
__device__ __forceinline__ uint32_t smem_u32(const void* p) {
    uint32_t a;
    asm("{ .reg .u64 t; cvta.to.shared.u64 t, %1; cvt.u32.u64 %0, t; }"
        : "=r"(a) : "l"(p));
    return a;
}

__global__ __launch_bounds__(256) void k_mma()
{
    extern __shared__ __align__(16) char smem[];
    uint32_t sb = smem_u32(smem);
    int tid = threadIdx.x, wid = tid >> 5, lane = tid & 31;
    int q = lane >> 2, rs = lane & 3;
    int wm = wid & 3, wn = wid >> 2;
    int n0 = blockIdx.x * 128, o0 = blockIdx.y * 128, z = blockIdx.z;
    int kb = z * KCH;

    const __nv_bfloat16* gb0 = g_shi + (size_t)n0 * SIGS;
    const __nv_bfloat16* gb1 = g_slo + (size_t)n0 * SIGS;
    const __nv_bfloat16* gb2 = g_whi + (size_t)o0 * SIGS;
    const __nv_bfloat16* gb3 = g_wlo + (size_t)o0 * SIGS;

    auto issue = [&](int c) {
        uint32_t sdst = sb + (c & 1) * BUF_B;
        int k0 = kb + c * 32;
        #pragma unroll
        for (int i = 0; i < 8; i++) {
            int idx = tid + 256 * i;
            int arr = idx >> 9;
            int r = (idx >> 2) & 127;
            int seg = idx & 3;
            const __nv_bfloat16* gp =
                (arr == 0 ? gb0 : arr == 1 ? gb1 : arr == 2 ? gb2 : gb3)
                + (size_t)r * SIGS + k0 + seg * 8;
            uint32_t sp = sdst + arr * ARR_B + r * (RST * 2) + seg * 16;
            asm volatile("cp.async.cg.shared.global [%0], [%1], 16;"
                         :: "r"(sp), "l"(gp));
        }
        asm volatile("cp.async.commit_group;" ::: "memory");
    };

    float acc[2][8][4];
    #pragma unroll
    for (int mt = 0; mt < 2; mt++)
        #pragma unroll
        for (int nt = 0; nt < 8; nt++)
            #pragma unroll
            for (int j = 0; j < 4; j++) acc[mt][nt][j] = 0.f;

    issue(0);
    issue(1);

    for (int c = 0; c < NCH; c++) {
        if (c + 2 < NCH)
            asm volatile("cp.async.wait_group 1;" ::: "memory");
        else
            asm volatile("cp.async.wait_group 0;" ::: "memory");
        __syncthreads();

        const __nv_bfloat16* Ah =
            (const __nv_bfloat16*)(smem + (c & 1) * BUF_B);
        const __nv_bfloat16* Al = Ah + 128 * RST;
        const __nv_bfloat16* Bh = Al + 128 * RST;
        const __nv_bfloat16* Bl = Bh + 128 * RST;

        #pragma unroll
        for (int kk = 0; kk < 2; kk++) {
            int col = 2 * rs + 16 * kk;
            uint32_t af[2][2][4];
            #pragma unroll
            for (int mt = 0; mt < 2; mt++) {
                int r0 = 32 * wm + 16 * mt + q;
                af[mt][0][0] = ld32h(Ah + r0 * RST + col);
                af[mt][0][1] = ld32h(Ah + (r0 + 8) * RST + col);
                af[mt][0][2] = ld32h(Ah + r0 * RST + col + 8);
                af[mt][0][3] = ld32h(Ah + (r0 + 8) * RST + col + 8);
                af[mt][1][0] = ld32h(Al + r0 * RST + col);
                af[mt][1][1] = ld32h(Al + (r0 + 8) * RST + col);
                af[mt][1][2] = ld32h(Al + r0 * RST + col + 8);
                af[mt][1][3] = ld32h(Al + (r0 + 8) * RST + col + 8);
            }
            uint32_t bfr[8][2][2];
            #pragma unroll
            for (int nt = 0; nt < 8; nt++) {
                int rn = 64 * wn + 8 * nt + q;
                bfr[nt][0][0] = ld32h(Bh + rn * RST + col);
                bfr[nt][0][1] = ld32h(Bh + rn * RST + col + 8);
                bfr[nt][1][0] = ld32h(Bl + rn * RST + col);
                bfr[nt][1][1] = ld32h(Bl + rn * RST + col + 8);
            }
            #pragma unroll
            for (int mt = 0; mt < 2; mt++)
                #pragma unroll
                for (int nt = 0; nt < 8; nt++) {
                    mma16816(acc[mt][nt], af[mt][0], bfr[nt][0]);
                    mma16816(acc[mt][nt], af[mt][0], bfr[nt][1]);
                    mma16816(acc[mt][nt], af[mt][1], bfr[nt][0]);
                }
        }
        __syncthreads();
        if (c + 2 < NCH) issue(c + 2);
    }

    float* pz = g_part + ((size_t)z * 256 + n0 + 32 * wm) * 256 + o0 + 64 * wn;
    #pragma unroll
    for (int mt = 0; mt < 2; mt++) {
        #pragma unroll
        for (int nt = 0; nt < 8; nt++) {
            int m = 16 * mt + q;
            int cc = 8 * nt + 2 * rs;
            float2 v01 = make_float2(acc[mt][nt][0], acc[mt][nt][1]);
            float2 v23 = make_float2(acc[mt][nt][2], acc[mt][nt][3]);
            *(float2*)&pz[(size_t)m * 256 + cc] = v01;
            *(float2*)&pz[(size_t)(m + 8) * 256 + cc] = v23;
        }
    }
}

// ============================================================
// K5: reduce splitK partials + bias
// ============================================================
__global__ void k_red(const float* __restrict__ lb, float* __restrict__ out)
{
    int n = blockIdx.x, o = threadIdx.x;
    float s = lb[o];
    #pragma unroll 4
    for (int z = 0; z < SPLITK; z++)
        s += g_part[((size_t)z * 256 + n) * 256 + o];
    out[n * 256 + o] = s;
}

// ============================================================
extern "C" void kernel_launch(void* const* d_in, const int* in_sizes, int n_in,
                              void* d_out, int out_size)
{
    const float* q  = (const float*)d_in[0];
    const float* w1 = (const float*)d_in[4];
    const float* b1 = (const float*)d_in[5];
    const float* w2 = (const float*)d_in[6];
    const float* b2 = (const float*)d_in[7];
    const float* lw = (const float*)d_in[8];
    const float* lb = (const float*)d_in[9];
    float* out = (float*)d_out;

    cudaFuncSetAttribute(k_front, cudaFuncAttributeMaxDynamicSharedMemorySize,
                         24256 * 4);
    cudaFuncSetAttribute(k_mma, cudaFuncAttributeMaxDynamicSharedMemorySize,
                         2 * BUF_B);
    k_front<<<NB, 256, 24256 * 4>>>(q, w1, b1, w2, b2);
    k_sig<<<NB, 256>>>();
    k_wprep<<<SIGS / 32, 256>>>(lw);
    k_mma<<<dim3(2, 2, SPLITK), 256, 2 * BUF_B>>>();
    k_red<<<256, 256>>>(lb, out);
}